// round 11
// baseline (speedup 1.0000x reference)
#include <cuda_runtime.h>

#ifndef B_DIM
#define B_DIM 8
#define N_DIM 8192
#define M_DIM 128
#endif

#define T_TAB 32          // table resolution
#define T_PAD 33          // padded row stride (bank-conflict mitigation)

constexpr int WARPS_PER_CTA = 8;
constexpr int PTS_PER_WARP  = 8;
constexpr int PTS_PER_CTA   = WARPS_PER_CTA * PTS_PER_WARP;  // 64
constexpr int THREADS       = WARPS_PER_CTA * 32;            // 256

constexpr int SMEM_TAB_BYTES = M_DIM * T_PAD * sizeof(float2);   // 33792
constexpr int SMEM_BYTES     = SMEM_TAB_BYTES + M_DIM * sizeof(float4);

typedef unsigned long long u64;

// Per-(batch, m) lookup table of the scalar map f -> MLP output.
// Entry t holds (v_t, v_{t+1} - v_t) for linear interpolation.
__device__ float2 g_table[B_DIM * M_DIM * T_TAB];

__device__ __forceinline__ float leaky(float x) { return fmaxf(x, 0.2f * x); }

__device__ __forceinline__ float mlp_exact(float f, float vx, float vy, float vz,
                                           const float* __restrict__ W1, const float* __restrict__ b1,
                                           const float* __restrict__ W2, const float* __restrict__ b2,
                                           const float* __restrict__ W3, const float* __restrict__ b3) {
    float h[4], g[4];
#pragma unroll
    for (int j = 0; j < 4; j++) {
        float z = fmaf(W1[4*j+0], f, fmaf(W1[4*j+1], vx,
                  fmaf(W1[4*j+2], vy, fmaf(W1[4*j+3], vz, b1[j]))));
        h[j] = leaky(z);
    }
#pragma unroll
    for (int i = 0; i < 4; i++) {
        float z = fmaf(W2[4*i+0], h[0], fmaf(W2[4*i+1], h[1],
                  fmaf(W2[4*i+2], h[2], fmaf(W2[4*i+3], h[3], b2[i]))));
        g[i] = leaky(z);
    }
    return fmaf(W3[0], g[0], fmaf(W3[1], g[1], fmaf(W3[2], g[2], fmaf(W3[3], g[3], b3[0]))));
}

__global__ void build_table(const float* __restrict__ V,
                            const float* __restrict__ W1, const float* __restrict__ b1,
                            const float* __restrict__ W2, const float* __restrict__ b2,
                            const float* __restrict__ W3, const float* __restrict__ b3) {
    const int idx = blockIdx.x * blockDim.x + threadIdx.x;   // [0, B*M*T)
    if (idx >= B_DIM * M_DIM * T_TAB) return;
    const int t  = idx & (T_TAB - 1);
    const int bm = idx / T_TAB;
    const int m  = bm & (M_DIM - 1);
    const int b  = bm / M_DIM;

    const float vx = __ldg(&V[(b * M_DIM + m) * 3 + 0]);
    const float vy = __ldg(&V[(b * M_DIM + m) * 3 + 1]);
    const float vz = __ldg(&V[(b * M_DIM + m) * 3 + 2]);

    const float f0 = (float)t * (1.0f / T_TAB);
    const float f1 = (float)(t + 1) * (1.0f / T_TAB);
    const float v0 = mlp_exact(f0, vx, vy, vz, W1, b1, W2, b2, W3, b3);
    const float v1 = mlp_exact(f1, vx, vy, vz, W1, b1, W2, b2, W3, b3);
    g_table[idx] = make_float2(v0, v1 - v0);
}

// ---------- packed f32x2 helpers (Blackwell) ----------
__device__ __forceinline__ u64 pack2(float lo, float hi) {
    u64 r; asm("mov.b64 %0, {%1,%2};" : "=l"(r) : "f"(lo), "f"(hi)); return r;
}
__device__ __forceinline__ void unpack2(u64 v, float& lo, float& hi) {
    asm("mov.b64 {%0,%1}, %2;" : "=f"(lo), "=f"(hi) : "l"(v));
}
__device__ __forceinline__ u64 fma2(u64 a, u64 b, u64 c) {
    u64 d; asm("fma.rn.f32x2 %0, %1, %2, %3;" : "=l"(d) : "l"(a), "l"(b), "l"(c)); return d;
}
__device__ __forceinline__ u64 mul2(u64 a, u64 b) {
    u64 d; asm("mul.rn.f32x2 %0, %1, %2;" : "=l"(d) : "l"(a), "l"(b)); return d;
}
__device__ __forceinline__ u64 add2(u64 a, u64 b) {
    u64 d; asm("add.rn.f32x2 %0, %1, %2;" : "=l"(d) : "l"(a), "l"(b)); return d;
}
__device__ __forceinline__ float sqrt_approx(float x) {
    float r; asm("sqrt.approx.f32 %0, %1;" : "=f"(r) : "f"(x)); return r;
}
__device__ __forceinline__ float rcp_approx(float x) {
    float r; asm("rcp.approx.f32 %0, %1;" : "=f"(r) : "f"(x)); return r;
}

__global__ void __launch_bounds__(THREADS)
featuration_kernel(const float* __restrict__ xyz,   // [B,3,N]
                   const float* __restrict__ V,     // [B,M,3]
                   float* __restrict__ out)         // [B,N,M]
{
    extern __shared__ unsigned char smem_raw[];
    float2* tab = reinterpret_cast<float2*>(smem_raw);                      // [M][T_PAD]
    float4* Vsm = reinterpret_cast<float4*>(smem_raw + SMEM_TAB_BYTES);     // [M]

    const int b   = blockIdx.y;
    const int tid = threadIdx.x;

    // ---- load this batch's table into smem (coalesced) ----
    {
        const float2* gsrc = g_table + (size_t)b * M_DIM * T_TAB;
        for (int idx = tid; idx < M_DIM * T_TAB; idx += THREADS) {
            const int m = idx >> 5;            // / T_TAB
            const int t = idx & (T_TAB - 1);
            tab[m * T_PAD + t] = __ldg(gsrc + idx);
        }
    }
    if (tid < M_DIM) {
        const float vx = __ldg(&V[(b * M_DIM + tid) * 3 + 0]);
        const float vy = __ldg(&V[(b * M_DIM + tid) * 3 + 1]);
        const float vz = __ldg(&V[(b * M_DIM + tid) * 3 + 2]);
        Vsm[tid] = make_float4(vx, vy, vz, 0.0f);
    }
    __syncthreads();

    const int warp = tid >> 5;
    const int lane = tid & 31;

    // lane owns m = 4*lane .. 4*lane+3 ; negated V packed across m-pairs
    const float4 v0 = Vsm[4 * lane + 0];
    const float4 v1 = Vsm[4 * lane + 1];
    const float4 v2 = Vsm[4 * lane + 2];
    const float4 v3 = Vsm[4 * lane + 3];
    const u64 nvxA = pack2(-v0.x, -v1.x), nvyA = pack2(-v0.y, -v1.y), nvzA = pack2(-v0.z, -v1.z);
    const u64 nvxB = pack2(-v2.x, -v3.x), nvyB = pack2(-v2.y, -v3.y), nvzB = pack2(-v2.z, -v3.z);

    const float2* __restrict__ t0 = tab + (4 * lane + 0) * T_PAD;
    const float2* __restrict__ t1 = tab + (4 * lane + 1) * T_PAD;
    const float2* __restrict__ t2 = tab + (4 * lane + 2) * T_PAD;
    const float2* __restrict__ t3 = tab + (4 * lane + 3) * T_PAD;

    const float* xb = xyz + (size_t)b * 3 * N_DIM;
    float* outb = out + (size_t)b * N_DIM * M_DIM;

    const int n_base = blockIdx.x * PTS_PER_CTA + warp * PTS_PER_WARP;

#pragma unroll
    for (int p = 0; p < PTS_PER_WARP; p++) {
        const int n = n_base + p;
        const float px = __ldg(&xb[n]);
        const float py = __ldg(&xb[N_DIM + n]);
        const float pz = __ldg(&xb[2 * N_DIM + n]);
        const u64 pxs = pack2(px, px), pys = pack2(py, py), pzs = pack2(pz, pz);

        // squared distances, packed across m-pairs
        const u64 dxA = add2(pxs, nvxA), dyA = add2(pys, nvyA), dzA = add2(pzs, nvzA);
        const u64 sA  = fma2(dxA, dxA, fma2(dyA, dyA, mul2(dzA, dzA)));
        const u64 dxB = add2(pxs, nvxB), dyB = add2(pys, nvyB), dzB = add2(pzs, nvzB);
        const u64 sB  = fma2(dxB, dxB, fma2(dyB, dyB, mul2(dzB, dzB)));
        float s0, s1, s2, s3;
        unpack2(sA, s0, s1); unpack2(sB, s2, s3);

        // butterfly on squared values (sqrt is monotone); elem sqrts overlap it
        float mns = fminf(fminf(s0, s1), fminf(s2, s3));
        float mxs = fmaxf(fmaxf(s0, s1), fmaxf(s2, s3));
#pragma unroll
        for (int off = 16; off > 0; off >>= 1) {
            mns = fminf(mns, __shfl_xor_sync(0xFFFFFFFFu, mns, off));
            mxs = fmaxf(mxs, __shfl_xor_sync(0xFFFFFFFFu, mxs, off));
        }

        const float d0 = sqrt_approx(s0);
        const float d1 = sqrt_approx(s1);
        const float d2 = sqrt_approx(s2);
        const float d3 = sqrt_approx(s3);
        const float mn = sqrt_approx(mns);
        const float mx = sqrt_approx(mxs);
        const float denom = mx - mn;
        const float inv = (denom > 0.0f) ? rcp_approx(denom) : 0.0f;
        const float invT = inv * (float)T_TAB;
        const float nmT  = -mn * invT;           // x = d*invT + nmT in [0, T]

        const float x0 = fmaf(d0, invT, nmT);
        const float x1 = fmaf(d1, invT, nmT);
        const float x2 = fmaf(d2, invT, nmT);
        const float x3 = fmaf(d3, invT, nmT);
        const int i0 = min((int)x0, T_TAB - 1);
        const int i1 = min((int)x1, T_TAB - 1);
        const int i2 = min((int)x2, T_TAB - 1);
        const int i3 = min((int)x3, T_TAB - 1);
        const float2 e0 = t0[i0];
        const float2 e1 = t1[i1];
        const float2 e2 = t2[i2];
        const float2 e3 = t3[i3];
        const float fr0 = x0 - (float)i0;
        const float fr1 = x1 - (float)i1;
        const float fr2 = x2 - (float)i2;
        const float fr3 = x3 - (float)i3;

        float4 res;
        res.x = fmaf(fr0, e0.y, e0.x);
        res.y = fmaf(fr1, e1.y, e1.x);
        res.z = fmaf(fr2, e2.y, e2.x);
        res.w = fmaf(fr3, e3.y, e3.x);

        reinterpret_cast<float4*>(outb + (size_t)n * M_DIM)[lane] = res;
    }
}

extern "C" void kernel_launch(void* const* d_in, const int* in_sizes, int n_in,
                              void* d_out, int out_size) {
    const float* xyz = (const float*)d_in[0];
    const float* V   = (const float*)d_in[1];
    const float* W1  = (const float*)d_in[2];
    const float* b1  = (const float*)d_in[3];
    const float* W2  = (const float*)d_in[4];
    const float* b2  = (const float*)d_in[5];
    const float* W3  = (const float*)d_in[6];
    const float* b3  = (const float*)d_in[7];
    float* out = (float*)d_out;

    // Pass 1: build per-(b,m) scalar-function tables (tiny: 32K entries)
    const int total = B_DIM * M_DIM * T_TAB;
    build_table<<<(total + 255) / 256, 256>>>(V, W1, b1, W2, b2, W3, b3);

    // Pass 2: fused distance + normalize + smem-table lookup
    cudaFuncSetAttribute(featuration_kernel,
                         cudaFuncAttributeMaxDynamicSharedMemorySize, SMEM_BYTES);
    dim3 grid(N_DIM / PTS_PER_CTA, B_DIM);  // (128, 8)
    featuration_kernel<<<grid, THREADS, SMEM_BYTES>>>(xyz, V, out);
}

// round 12
// speedup vs baseline: 1.3479x; 1.3479x over previous
#include <cuda_runtime.h>

#ifndef B_DIM
#define B_DIM 8
#define N_DIM 8192
#define M_DIM 128
#endif

#define T_TAB 32          // table resolution

constexpr int WARPS_PER_CTA = 8;
constexpr int PTS_PER_WARP  = 8;
constexpr int PTS_PER_CTA   = WARPS_PER_CTA * PTS_PER_WARP;  // 64
constexpr int THREADS       = WARPS_PER_CTA * 32;            // 256

// transposed table: [T_TAB][M_DIM] float2 rows (t-major). Row = 1024B.
constexpr int SMEM_TAB_BYTES = T_TAB * M_DIM * sizeof(float2);   // 32768
constexpr int SMEM_BYTES     = SMEM_TAB_BYTES + M_DIM * sizeof(float4);

typedef unsigned long long u64;

// g_table layout: [b][t][m] (m fastest) -> coalesced build + coalesced smem fill
__device__ float2 g_table[B_DIM * T_TAB * M_DIM];

__device__ __forceinline__ float leaky(float x) { return fmaxf(x, 0.2f * x); }

__device__ __forceinline__ float mlp_exact(float f, float vx, float vy, float vz,
                                           const float* __restrict__ W1, const float* __restrict__ b1,
                                           const float* __restrict__ W2, const float* __restrict__ b2,
                                           const float* __restrict__ W3, const float* __restrict__ b3) {
    float h[4], g[4];
#pragma unroll
    for (int j = 0; j < 4; j++) {
        float z = fmaf(W1[4*j+0], f, fmaf(W1[4*j+1], vx,
                  fmaf(W1[4*j+2], vy, fmaf(W1[4*j+3], vz, b1[j]))));
        h[j] = leaky(z);
    }
#pragma unroll
    for (int i = 0; i < 4; i++) {
        float z = fmaf(W2[4*i+0], h[0], fmaf(W2[4*i+1], h[1],
                  fmaf(W2[4*i+2], h[2], fmaf(W2[4*i+3], h[3], b2[i]))));
        g[i] = leaky(z);
    }
    return fmaf(W3[0], g[0], fmaf(W3[1], g[1], fmaf(W3[2], g[2], fmaf(W3[3], g[3], b3[0]))));
}

__global__ void build_table(const float* __restrict__ V,
                            const float* __restrict__ W1, const float* __restrict__ b1,
                            const float* __restrict__ W2, const float* __restrict__ b2,
                            const float* __restrict__ W3, const float* __restrict__ b3) {
    const int idx = blockIdx.x * blockDim.x + threadIdx.x;   // [0, B*T*M)
    if (idx >= B_DIM * T_TAB * M_DIM) return;
    const int m  = idx & (M_DIM - 1);
    const int bt = idx >> 7;                  // / M_DIM
    const int t  = bt & (T_TAB - 1);
    const int b  = bt / T_TAB;

    const float vx = __ldg(&V[(b * M_DIM + m) * 3 + 0]);
    const float vy = __ldg(&V[(b * M_DIM + m) * 3 + 1]);
    const float vz = __ldg(&V[(b * M_DIM + m) * 3 + 2]);

    const float f0 = (float)t * (1.0f / T_TAB);
    const float f1 = (float)(t + 1) * (1.0f / T_TAB);
    const float v0 = mlp_exact(f0, vx, vy, vz, W1, b1, W2, b2, W3, b3);
    const float v1 = mlp_exact(f1, vx, vy, vz, W1, b1, W2, b2, W3, b3);
    g_table[idx] = make_float2(v0, v1 - v0);
}

// ---------- packed f32x2 helpers (Blackwell) ----------
__device__ __forceinline__ u64 pack2(float lo, float hi) {
    u64 r; asm("mov.b64 %0, {%1,%2};" : "=l"(r) : "f"(lo), "f"(hi)); return r;
}
__device__ __forceinline__ void unpack2(u64 v, float& lo, float& hi) {
    asm("mov.b64 {%0,%1}, %2;" : "=f"(lo), "=f"(hi) : "l"(v));
}
__device__ __forceinline__ u64 fma2(u64 a, u64 b, u64 c) {
    u64 d; asm("fma.rn.f32x2 %0, %1, %2, %3;" : "=l"(d) : "l"(a), "l"(b), "l"(c)); return d;
}
__device__ __forceinline__ u64 mul2(u64 a, u64 b) {
    u64 d; asm("mul.rn.f32x2 %0, %1, %2;" : "=l"(d) : "l"(a), "l"(b)); return d;
}
__device__ __forceinline__ u64 add2(u64 a, u64 b) {
    u64 d; asm("add.rn.f32x2 %0, %1, %2;" : "=l"(d) : "l"(a), "l"(b)); return d;
}
__device__ __forceinline__ float sqrt_approx(float x) {
    float r; asm("sqrt.approx.f32 %0, %1;" : "=f"(r) : "f"(x)); return r;
}
__device__ __forceinline__ float rcp_approx(float x) {
    float r; asm("rcp.approx.f32 %0, %1;" : "=f"(r) : "f"(x)); return r;
}

__global__ void __launch_bounds__(THREADS)
featuration_kernel(const float* __restrict__ xyz,   // [B,3,N]
                   const float* __restrict__ V,     // [B,M,3]
                   float* __restrict__ out)         // [B,N,M]
{
    extern __shared__ unsigned char smem_raw[];
    float2* tab = reinterpret_cast<float2*>(smem_raw);                      // [T_TAB][M_DIM]
    float4* Vsm = reinterpret_cast<float4*>(smem_raw + SMEM_TAB_BYTES);     // [M]

    const int b   = blockIdx.y;
    const int tid = threadIdx.x;

    // ---- load this batch's table into smem (coalesced, layout-preserving) ----
    {
        const float4* gsrc = reinterpret_cast<const float4*>(g_table + (size_t)b * T_TAB * M_DIM);
        float4* gdst = reinterpret_cast<float4*>(tab);
        for (int idx = tid; idx < T_TAB * M_DIM / 2; idx += THREADS)
            gdst[idx] = __ldg(gsrc + idx);
    }
    if (tid < M_DIM) {
        const float vx = __ldg(&V[(b * M_DIM + tid) * 3 + 0]);
        const float vy = __ldg(&V[(b * M_DIM + tid) * 3 + 1]);
        const float vz = __ldg(&V[(b * M_DIM + tid) * 3 + 2]);
        Vsm[tid] = make_float4(vx, vy, vz, 0.0f);
    }
    __syncthreads();

    const int warp = tid >> 5;
    const int lane = tid & 31;

    // STRIDED m ownership: lane owns m = lane + 32k, k=0..3.
    // LDS gather tab[t][m]: 8B double-bank index = (t*128 + lane + 32k) mod 64
    //                     = (lane + 32k) mod 64 -> all 32 lanes distinct -> conflict-free.
    const float4 v0 = Vsm[lane +  0];
    const float4 v1 = Vsm[lane + 32];
    const float4 v2 = Vsm[lane + 64];
    const float4 v3 = Vsm[lane + 96];
    const u64 nvxA = pack2(-v0.x, -v1.x), nvyA = pack2(-v0.y, -v1.y), nvzA = pack2(-v0.z, -v1.z);
    const u64 nvxB = pack2(-v2.x, -v3.x), nvyB = pack2(-v2.y, -v3.y), nvzB = pack2(-v2.z, -v3.z);

    const float* xb = xyz + (size_t)b * 3 * N_DIM;
    float* outb = out + (size_t)b * N_DIM * M_DIM;

    const int n_base = blockIdx.x * PTS_PER_CTA + warp * PTS_PER_WARP;

#pragma unroll
    for (int p = 0; p < PTS_PER_WARP; p++) {
        const int n = n_base + p;
        const float px = __ldg(&xb[n]);
        const float py = __ldg(&xb[N_DIM + n]);
        const float pz = __ldg(&xb[2 * N_DIM + n]);
        const u64 pxs = pack2(px, px), pys = pack2(py, py), pzs = pack2(pz, pz);

        // squared distances for m = lane, lane+32 (A) and lane+64, lane+96 (B)
        const u64 dxA = add2(pxs, nvxA), dyA = add2(pys, nvyA), dzA = add2(pzs, nvzA);
        const u64 sA  = fma2(dxA, dxA, fma2(dyA, dyA, mul2(dzA, dzA)));
        const u64 dxB = add2(pxs, nvxB), dyB = add2(pys, nvyB), dzB = add2(pzs, nvzB);
        const u64 sB  = fma2(dxB, dxB, fma2(dyB, dyB, mul2(dzB, dzB)));
        float s0, s1, s2, s3;
        unpack2(sA, s0, s1); unpack2(sB, s2, s3);

        // butterfly on squared values (sqrt is monotone); elem sqrts overlap it
        float mns = fminf(fminf(s0, s1), fminf(s2, s3));
        float mxs = fmaxf(fmaxf(s0, s1), fmaxf(s2, s3));
#pragma unroll
        for (int off = 16; off > 0; off >>= 1) {
            mns = fminf(mns, __shfl_xor_sync(0xFFFFFFFFu, mns, off));
            mxs = fmaxf(mxs, __shfl_xor_sync(0xFFFFFFFFu, mxs, off));
        }

        const float d0 = sqrt_approx(s0);
        const float d1 = sqrt_approx(s1);
        const float d2 = sqrt_approx(s2);
        const float d3 = sqrt_approx(s3);
        const float mn = sqrt_approx(mns);
        const float mx = sqrt_approx(mxs);
        const float denom = mx - mn;
        const float inv = (denom > 0.0f) ? rcp_approx(denom) : 0.0f;
        const float invT = inv * (float)T_TAB;
        const float nmT  = -mn * invT;           // x = d*invT + nmT in [0, T]

        const float x0 = fmaf(d0, invT, nmT);
        const float x1 = fmaf(d1, invT, nmT);
        const float x2 = fmaf(d2, invT, nmT);
        const float x3 = fmaf(d3, invT, nmT);
        const int i0 = min((int)x0, T_TAB - 1);
        const int i1 = min((int)x1, T_TAB - 1);
        const int i2 = min((int)x2, T_TAB - 1);
        const int i3 = min((int)x3, T_TAB - 1);

        // conflict-free gathers
        const float2 e0 = tab[i0 * M_DIM + lane +  0];
        const float2 e1 = tab[i1 * M_DIM + lane + 32];
        const float2 e2 = tab[i2 * M_DIM + lane + 64];
        const float2 e3 = tab[i3 * M_DIM + lane + 96];
        const float fr0 = x0 - (float)i0;
        const float fr1 = x1 - (float)i1;
        const float fr2 = x2 - (float)i2;
        const float fr3 = x3 - (float)i3;

        // four coalesced 128B stores (lane-strided m layout)
        float* dst = outb + (size_t)n * M_DIM + lane;
        dst[ 0] = fmaf(fr0, e0.y, e0.x);
        dst[32] = fmaf(fr1, e1.y, e1.x);
        dst[64] = fmaf(fr2, e2.y, e2.x);
        dst[96] = fmaf(fr3, e3.y, e3.x);
    }
}

extern "C" void kernel_launch(void* const* d_in, const int* in_sizes, int n_in,
                              void* d_out, int out_size) {
    const float* xyz = (const float*)d_in[0];
    const float* V   = (const float*)d_in[1];
    const float* W1  = (const float*)d_in[2];
    const float* b1  = (const float*)d_in[3];
    const float* W2  = (const float*)d_in[4];
    const float* b2  = (const float*)d_in[5];
    const float* W3  = (const float*)d_in[6];
    const float* b3  = (const float*)d_in[7];
    float* out = (float*)d_out;

    // Pass 1: build per-(b,t,m) scalar-function tables (32K entries)
    const int total = B_DIM * T_TAB * M_DIM;
    build_table<<<(total + 255) / 256, 256>>>(V, W1, b1, W2, b2, W3, b3);

    // Pass 2: fused distance + normalize + conflict-free smem-table lookup
    cudaFuncSetAttribute(featuration_kernel,
                         cudaFuncAttributeMaxDynamicSharedMemorySize, SMEM_BYTES);
    dim3 grid(N_DIM / PTS_PER_CTA, B_DIM);  // (128, 8)
    featuration_kernel<<<grid, THREADS, SMEM_BYTES>>>(xyz, V, out);
}

// round 14
// speedup vs baseline: 1.3500x; 1.0016x over previous
#include <cuda_runtime.h>

#ifndef B_DIM
#define B_DIM 8
#define N_DIM 8192
#define M_DIM 128
#endif

#define T_TAB 32          // table resolution
#define T_ROWS 33         // +1 clamp row (t=32 holds (g(1), 0))

constexpr int WARPS_PER_CTA = 8;
constexpr int THREADS       = WARPS_PER_CTA * 32;            // 256

constexpr int PTS_PER_TILE  = 16;                            // 2 per warp per tile
constexpr int TILES_PER_B   = N_DIM / PTS_PER_TILE;          // 512
constexpr int CTAS_PER_B    = 74;                            // 8*74 = 592 = 148*4
constexpr int GRID_CTAS     = B_DIM * CTAS_PER_B;            // 592

// transposed table: [T_ROWS][M_DIM] float2 rows (t-major). Row = 1024B.
constexpr int SMEM_TAB_BYTES = T_ROWS * M_DIM * sizeof(float2);  // 33792
constexpr int SMEM_BYTES     = SMEM_TAB_BYTES + M_DIM * sizeof(float4);

typedef unsigned long long u64;

// g_table layout: [b][t][m] (m fastest)
__device__ float2 g_table[B_DIM * T_ROWS * M_DIM];

__device__ __forceinline__ float leaky(float x) { return fmaxf(x, 0.2f * x); }

__device__ __forceinline__ float mlp_exact(float f, float vx, float vy, float vz,
                                           const float* __restrict__ W1, const float* __restrict__ b1,
                                           const float* __restrict__ W2, const float* __restrict__ b2,
                                           const float* __restrict__ W3, const float* __restrict__ b3) {
    float h[4], g[4];
#pragma unroll
    for (int j = 0; j < 4; j++) {
        float z = fmaf(W1[4*j+0], f, fmaf(W1[4*j+1], vx,
                  fmaf(W1[4*j+2], vy, fmaf(W1[4*j+3], vz, b1[j]))));
        h[j] = leaky(z);
    }
#pragma unroll
    for (int i = 0; i < 4; i++) {
        float z = fmaf(W2[4*i+0], h[0], fmaf(W2[4*i+1], h[1],
                  fmaf(W2[4*i+2], h[2], fmaf(W2[4*i+3], h[3], b2[i]))));
        g[i] = leaky(z);
    }
    return fmaf(W3[0], g[0], fmaf(W3[1], g[1], fmaf(W3[2], g[2], fmaf(W3[3], g[3], b3[0]))));
}

__global__ void build_table(const float* __restrict__ V,
                            const float* __restrict__ W1, const float* __restrict__ b1,
                            const float* __restrict__ W2, const float* __restrict__ b2,
                            const float* __restrict__ W3, const float* __restrict__ b3) {
    const int idx = blockIdx.x * blockDim.x + threadIdx.x;   // [0, B*T_ROWS*M)
    if (idx >= B_DIM * T_ROWS * M_DIM) return;
    const int m  = idx & (M_DIM - 1);
    const int bt = idx >> 7;                  // / M_DIM
    const int t  = bt % T_ROWS;
    const int b  = bt / T_ROWS;

    const float vx = __ldg(&V[(b * M_DIM + m) * 3 + 0]);
    const float vy = __ldg(&V[(b * M_DIM + m) * 3 + 1]);
    const float vz = __ldg(&V[(b * M_DIM + m) * 3 + 2]);

    const int t0c = (t < T_TAB) ? t : T_TAB;             // clamp row maps to f=1
    const int t1c = (t + 1 < T_TAB) ? (t + 1) : T_TAB;
    const float f0 = (float)t0c * (1.0f / T_TAB);
    const float f1 = (float)t1c * (1.0f / T_TAB);
    const float v0 = mlp_exact(f0, vx, vy, vz, W1, b1, W2, b2, W3, b3);
    const float v1 = mlp_exact(f1, vx, vy, vz, W1, b1, W2, b2, W3, b3);
    g_table[idx] = make_float2(v0, v1 - v0);
}

// ---------- packed f32x2 helpers (Blackwell) ----------
__device__ __forceinline__ u64 pack2(float lo, float hi) {
    u64 r; asm("mov.b64 %0, {%1,%2};" : "=l"(r) : "f"(lo), "f"(hi)); return r;
}
__device__ __forceinline__ void unpack2(u64 v, float& lo, float& hi) {
    asm("mov.b64 {%0,%1}, %2;" : "=f"(lo), "=f"(hi) : "l"(v));
}
__device__ __forceinline__ u64 fma2(u64 a, u64 b, u64 c) {
    u64 d; asm("fma.rn.f32x2 %0, %1, %2, %3;" : "=l"(d) : "l"(a), "l"(b), "l"(c)); return d;
}
__device__ __forceinline__ u64 mul2(u64 a, u64 b) {
    u64 d; asm("mul.rn.f32x2 %0, %1, %2;" : "=l"(d) : "l"(a), "l"(b)); return d;
}
__device__ __forceinline__ u64 add2(u64 a, u64 b) {
    u64 d; asm("add.rn.f32x2 %0, %1, %2;" : "=l"(d) : "l"(a), "l"(b)); return d;
}
__device__ __forceinline__ float sqrt_approx(float x) {
    float r; asm("sqrt.approx.f32 %0, %1;" : "=f"(r) : "f"(x)); return r;
}
__device__ __forceinline__ float rcp_approx(float x) {
    float r; asm("rcp.approx.f32 %0, %1;" : "=f"(r) : "f"(x)); return r;
}

__global__ void __launch_bounds__(THREADS)
featuration_kernel(const float* __restrict__ xyz,   // [B,3,N]
                   const float* __restrict__ V,     // [B,M,3]
                   float* __restrict__ out)         // [B,N,M]
{
    extern __shared__ unsigned char smem_raw[];
    float2* tab = reinterpret_cast<float2*>(smem_raw);                      // [T_ROWS][M_DIM]
    float4* Vsm = reinterpret_cast<float4*>(smem_raw + SMEM_TAB_BYTES);     // [M]

    const int b = blockIdx.x / CTAS_PER_B;
    const int k = blockIdx.x - b * CTAS_PER_B;
    const int tid = threadIdx.x;

    // ---- load this batch's table into smem (coalesced, layout-preserving) ----
    {
        const float4* gsrc = reinterpret_cast<const float4*>(g_table + (size_t)b * T_ROWS * M_DIM);
        float4* gdst = reinterpret_cast<float4*>(tab);
        for (int idx = tid; idx < T_ROWS * M_DIM / 2; idx += THREADS)
            gdst[idx] = __ldg(gsrc + idx);
    }
    if (tid < M_DIM) {
        const float vx = __ldg(&V[(b * M_DIM + tid) * 3 + 0]);
        const float vy = __ldg(&V[(b * M_DIM + tid) * 3 + 1]);
        const float vz = __ldg(&V[(b * M_DIM + tid) * 3 + 2]);
        Vsm[tid] = make_float4(vx, vy, vz, 0.0f);
    }
    __syncthreads();

    const int warp = tid >> 5;
    const int lane = tid & 31;

    // STRIDED m ownership: lane owns m = lane + 32k, k=0..3 (conflict-free LDS gather)
    const float4 v0 = Vsm[lane +  0];
    const float4 v1 = Vsm[lane + 32];
    const float4 v2 = Vsm[lane + 64];
    const float4 v3 = Vsm[lane + 96];
    const u64 nvxA = pack2(-v0.x, -v1.x), nvyA = pack2(-v0.y, -v1.y), nvzA = pack2(-v0.z, -v1.z);
    const u64 nvxB = pack2(-v2.x, -v3.x), nvyB = pack2(-v2.y, -v3.y), nvzB = pack2(-v2.z, -v3.z);

    const float* xb = xyz + (size_t)b * 3 * N_DIM;
    float* outb = out + (size_t)b * N_DIM * M_DIM;

    // ---- balanced tile loop: one batch per CTA, 512 tiles / 74 CTAs ----
    for (int t = k; t < TILES_PER_B; t += CTAS_PER_B) {
        const int n0 = t * PTS_PER_TILE + warp * 2;
#pragma unroll
        for (int p = 0; p < 2; p++) {
            const int n = n0 + p;
            const float px = __ldg(&xb[n]);
            const float py = __ldg(&xb[N_DIM + n]);
            const float pz = __ldg(&xb[2 * N_DIM + n]);
            const u64 pxs = pack2(px, px), pys = pack2(py, py), pzs = pack2(pz, pz);

            // squared distances for m = lane, lane+32 (A) and lane+64, lane+96 (B)
            const u64 dxA = add2(pxs, nvxA), dyA = add2(pys, nvyA), dzA = add2(pzs, nvzA);
            const u64 sA  = fma2(dxA, dxA, fma2(dyA, dyA, mul2(dzA, dzA)));
            const u64 dxB = add2(pxs, nvxB), dyB = add2(pys, nvyB), dzB = add2(pzs, nvzB);
            const u64 sB  = fma2(dxB, dxB, fma2(dyB, dyB, mul2(dzB, dzB)));
            float s0, s1, s2, s3;
            unpack2(sA, s0, s1); unpack2(sB, s2, s3);

            // butterfly on squared values (sqrt is monotone)
            float mns = fminf(fminf(s0, s1), fminf(s2, s3));
            float mxs = fmaxf(fmaxf(s0, s1), fmaxf(s2, s3));
#pragma unroll
            for (int off = 16; off > 0; off >>= 1) {
                mns = fminf(mns, __shfl_xor_sync(0xFFFFFFFFu, mns, off));
                mxs = fmaxf(mxs, __shfl_xor_sync(0xFFFFFFFFu, mxs, off));
            }

            const float d0 = sqrt_approx(s0);
            const float d1 = sqrt_approx(s1);
            const float d2 = sqrt_approx(s2);
            const float d3 = sqrt_approx(s3);
            const float mn = sqrt_approx(mns);
            const float mx = sqrt_approx(mxs);
            const float denom = mx - mn;
            const float inv = (denom > 0.0f) ? rcp_approx(denom) : 0.0f;
            const float invT = inv * (float)T_TAB;
            const float nmT  = -mn * invT;           // x = d*invT + nmT in [0, T(+eps)]

            const float x0 = fmaxf(fmaf(d0, invT, nmT), 0.0f);
            const float x1 = fmaxf(fmaf(d1, invT, nmT), 0.0f);
            const float x2 = fmaxf(fmaf(d2, invT, nmT), 0.0f);
            const float x3 = fmaxf(fmaf(d3, invT, nmT), 0.0f);
            // no upper clamp needed: row 32 is a (g(1), 0) guard row; x <= 32+eps
            const int i0 = (int)x0;
            const int i1 = (int)x1;
            const int i2 = (int)x2;
            const int i3 = (int)x3;

            // conflict-free gathers
            const float2 e0 = tab[i0 * M_DIM + lane +  0];
            const float2 e1 = tab[i1 * M_DIM + lane + 32];
            const float2 e2 = tab[i2 * M_DIM + lane + 64];
            const float2 e3 = tab[i3 * M_DIM + lane + 96];
            const float fr0 = x0 - (float)i0;
            const float fr1 = x1 - (float)i1;
            const float fr2 = x2 - (float)i2;
            const float fr3 = x3 - (float)i3;

            // four coalesced 128B stores (lane-strided m layout)
            float* dst = outb + (size_t)n * M_DIM + lane;
            dst[ 0] = fmaf(fr0, e0.y, e0.x);
            dst[32] = fmaf(fr1, e1.y, e1.x);
            dst[64] = fmaf(fr2, e2.y, e2.x);
            dst[96] = fmaf(fr3, e3.y, e3.x);
        }
    }
}

extern "C" void kernel_launch(void* const* d_in, const int* in_sizes, int n_in,
                              void* d_out, int out_size) {
    const float* xyz = (const float*)d_in[0];
    const float* V   = (const float*)d_in[1];
    const float* W1  = (const float*)d_in[2];
    const float* b1  = (const float*)d_in[3];
    const float* W2  = (const float*)d_in[4];
    const float* b2  = (const float*)d_in[5];
    const float* W3  = (const float*)d_in[6];
    const float* b3  = (const float*)d_in[7];
    float* out = (float*)d_out;

    // Pass 1: build per-(b,t,m) scalar-function tables (33 rows incl. clamp row)
    const int total = B_DIM * T_ROWS * M_DIM;
    build_table<<<(total + 255) / 256, 256>>>(V, W1, b1, W2, b2, W3, b3);

    // Pass 2: single balanced wave — 592 CTAs = 148 SMs x 4
    cudaFuncSetAttribute(featuration_kernel,
                         cudaFuncAttributeMaxDynamicSharedMemorySize, SMEM_BYTES);
    featuration_kernel<<<GRID_CTAS, THREADS, SMEM_BYTES>>>(xyz, V, out);
}

// round 15
// speedup vs baseline: 1.3802x; 1.0224x over previous
#include <cuda_runtime.h>

#ifndef B_DIM
#define B_DIM 8
#define N_DIM 8192
#define M_DIM 128
#endif

#define T_TAB 32          // table resolution
#define T_ROWS 33         // +1 clamp row (t=32 holds (g(1), 0))

constexpr int WARPS_PER_CTA = 8;
constexpr int THREADS       = WARPS_PER_CTA * 32;            // 256

constexpr int PTS_PER_TILE  = 16;                            // 2 per warp per tile
constexpr int TILES_PER_B   = N_DIM / PTS_PER_TILE;          // 512
constexpr int CTAS_PER_B    = 111;                           // 8*111 = 888 = 148*6
constexpr int GRID_CTAS     = B_DIM * CTAS_PER_B;            // 888

// transposed table: [T_ROWS][M_DIM] float2 rows (t-major). Row = 1024B.
constexpr int SMEM_TAB_BYTES = T_ROWS * M_DIM * sizeof(float2);  // 33792
constexpr int SMEM_BYTES     = SMEM_TAB_BYTES + M_DIM * sizeof(float4);

typedef unsigned long long u64;

// g_table layout: [b][t][m] (m fastest)
__device__ float2 g_table[B_DIM * T_ROWS * M_DIM];

__device__ __forceinline__ float leaky(float x) { return fmaxf(x, 0.2f * x); }

__device__ __forceinline__ float mlp_exact(float f, float vx, float vy, float vz,
                                           const float* __restrict__ W1, const float* __restrict__ b1,
                                           const float* __restrict__ W2, const float* __restrict__ b2,
                                           const float* __restrict__ W3, const float* __restrict__ b3) {
    float h[4], g[4];
#pragma unroll
    for (int j = 0; j < 4; j++) {
        float z = fmaf(W1[4*j+0], f, fmaf(W1[4*j+1], vx,
                  fmaf(W1[4*j+2], vy, fmaf(W1[4*j+3], vz, b1[j]))));
        h[j] = leaky(z);
    }
#pragma unroll
    for (int i = 0; i < 4; i++) {
        float z = fmaf(W2[4*i+0], h[0], fmaf(W2[4*i+1], h[1],
                  fmaf(W2[4*i+2], h[2], fmaf(W2[4*i+3], h[3], b2[i]))));
        g[i] = leaky(z);
    }
    return fmaf(W3[0], g[0], fmaf(W3[1], g[1], fmaf(W3[2], g[2], fmaf(W3[3], g[3], b3[0]))));
}

__global__ void build_table(const float* __restrict__ V,
                            const float* __restrict__ W1, const float* __restrict__ b1,
                            const float* __restrict__ W2, const float* __restrict__ b2,
                            const float* __restrict__ W3, const float* __restrict__ b3) {
    const int idx = blockIdx.x * blockDim.x + threadIdx.x;   // [0, B*T_ROWS*M)
    if (idx >= B_DIM * T_ROWS * M_DIM) return;
    const int m  = idx & (M_DIM - 1);
    const int bt = idx >> 7;                  // / M_DIM
    const int t  = bt % T_ROWS;
    const int b  = bt / T_ROWS;

    const float vx = __ldg(&V[(b * M_DIM + m) * 3 + 0]);
    const float vy = __ldg(&V[(b * M_DIM + m) * 3 + 1]);
    const float vz = __ldg(&V[(b * M_DIM + m) * 3 + 2]);

    const int t0c = (t < T_TAB) ? t : T_TAB;             // clamp row maps to f=1
    const int t1c = (t + 1 < T_TAB) ? (t + 1) : T_TAB;
    const float f0 = (float)t0c * (1.0f / T_TAB);
    const float f1 = (float)t1c * (1.0f / T_TAB);
    const float v0 = mlp_exact(f0, vx, vy, vz, W1, b1, W2, b2, W3, b3);
    const float v1 = mlp_exact(f1, vx, vy, vz, W1, b1, W2, b2, W3, b3);
    g_table[idx] = make_float2(v0, v1 - v0);
}

// ---------- packed f32x2 helpers (Blackwell) ----------
__device__ __forceinline__ u64 pack2(float lo, float hi) {
    u64 r; asm("mov.b64 %0, {%1,%2};" : "=l"(r) : "f"(lo), "f"(hi)); return r;
}
__device__ __forceinline__ void unpack2(u64 v, float& lo, float& hi) {
    asm("mov.b64 {%0,%1}, %2;" : "=f"(lo), "=f"(hi) : "l"(v));
}
__device__ __forceinline__ u64 fma2(u64 a, u64 b, u64 c) {
    u64 d; asm("fma.rn.f32x2 %0, %1, %2, %3;" : "=l"(d) : "l"(a), "l"(b), "l"(c)); return d;
}
__device__ __forceinline__ u64 mul2(u64 a, u64 b) {
    u64 d; asm("mul.rn.f32x2 %0, %1, %2;" : "=l"(d) : "l"(a), "l"(b)); return d;
}
__device__ __forceinline__ u64 add2(u64 a, u64 b) {
    u64 d; asm("add.rn.f32x2 %0, %1, %2;" : "=l"(d) : "l"(a), "l"(b)); return d;
}
__device__ __forceinline__ float sqrt_approx(float x) {
    float r; asm("sqrt.approx.f32 %0, %1;" : "=f"(r) : "f"(x)); return r;
}
__device__ __forceinline__ float rcp_approx(float x) {
    float r; asm("rcp.approx.f32 %0, %1;" : "=f"(r) : "f"(x)); return r;
}

__global__ void __launch_bounds__(THREADS, 6)
featuration_kernel(const float* __restrict__ xyz,   // [B,3,N]
                   const float* __restrict__ V,     // [B,M,3]
                   float* __restrict__ out)         // [B,N,M]
{
    extern __shared__ unsigned char smem_raw[];
    float2* tab = reinterpret_cast<float2*>(smem_raw);                      // [T_ROWS][M_DIM]
    float4* Vsm = reinterpret_cast<float4*>(smem_raw + SMEM_TAB_BYTES);     // [M]

    const int b = blockIdx.x / CTAS_PER_B;
    const int k = blockIdx.x - b * CTAS_PER_B;
    const int tid = threadIdx.x;

    // ---- load this batch's table into smem (coalesced, layout-preserving) ----
    {
        const float4* gsrc = reinterpret_cast<const float4*>(g_table + (size_t)b * T_ROWS * M_DIM);
        float4* gdst = reinterpret_cast<float4*>(tab);
        for (int idx = tid; idx < T_ROWS * M_DIM / 2; idx += THREADS)
            gdst[idx] = __ldg(gsrc + idx);
    }
    if (tid < M_DIM) {
        const float vx = __ldg(&V[(b * M_DIM + tid) * 3 + 0]);
        const float vy = __ldg(&V[(b * M_DIM + tid) * 3 + 1]);
        const float vz = __ldg(&V[(b * M_DIM + tid) * 3 + 2]);
        Vsm[tid] = make_float4(vx, vy, vz, 0.0f);
    }
    __syncthreads();

    const int warp = tid >> 5;
    const int lane = tid & 31;

    // STRIDED m ownership: lane owns m = lane + 32k, k=0..3 (conflict-free LDS gather)
    const float4 v0 = Vsm[lane +  0];
    const float4 v1 = Vsm[lane + 32];
    const float4 v2 = Vsm[lane + 64];
    const float4 v3 = Vsm[lane + 96];
    const u64 nvxA = pack2(-v0.x, -v1.x), nvyA = pack2(-v0.y, -v1.y), nvzA = pack2(-v0.z, -v1.z);
    const u64 nvxB = pack2(-v2.x, -v3.x), nvyB = pack2(-v2.y, -v3.y), nvzB = pack2(-v2.z, -v3.z);

    const float* xb = xyz + (size_t)b * 3 * N_DIM;
    float* outb = out + (size_t)b * N_DIM * M_DIM;

    // ---- tile loop: one batch per CTA group, 512 tiles / 111 CTAs ----
    for (int t = k; t < TILES_PER_B; t += CTAS_PER_B) {
        const int n0 = t * PTS_PER_TILE + warp * 2;
#pragma unroll
        for (int p = 0; p < 2; p++) {
            const int n = n0 + p;
            const float px = __ldg(&xb[n]);
            const float py = __ldg(&xb[N_DIM + n]);
            const float pz = __ldg(&xb[2 * N_DIM + n]);
            const u64 pxs = pack2(px, px), pys = pack2(py, py), pzs = pack2(pz, pz);

            // squared distances for m = lane, lane+32 (A) and lane+64, lane+96 (B)
            const u64 dxA = add2(pxs, nvxA), dyA = add2(pys, nvyA), dzA = add2(pzs, nvzA);
            const u64 sA  = fma2(dxA, dxA, fma2(dyA, dyA, mul2(dzA, dzA)));
            const u64 dxB = add2(pxs, nvxB), dyB = add2(pys, nvyB), dzB = add2(pzs, nvzB);
            const u64 sB  = fma2(dxB, dxB, fma2(dyB, dyB, mul2(dzB, dzB)));
            float s0, s1, s2, s3;
            unpack2(sA, s0, s1); unpack2(sB, s2, s3);

            // butterfly on squared values (sqrt is monotone)
            float mns = fminf(fminf(s0, s1), fminf(s2, s3));
            float mxs = fmaxf(fmaxf(s0, s1), fmaxf(s2, s3));
#pragma unroll
            for (int off = 16; off > 0; off >>= 1) {
                mns = fminf(mns, __shfl_xor_sync(0xFFFFFFFFu, mns, off));
                mxs = fmaxf(mxs, __shfl_xor_sync(0xFFFFFFFFu, mxs, off));
            }

            const float d0 = sqrt_approx(s0);
            const float d1 = sqrt_approx(s1);
            const float d2 = sqrt_approx(s2);
            const float d3 = sqrt_approx(s3);
            const float mn = sqrt_approx(mns);
            const float mx = sqrt_approx(mxs);
            const float denom = mx - mn;
            const float inv = (denom > 0.0f) ? rcp_approx(denom) : 0.0f;
            const float invT = inv * (float)T_TAB;
            const float nmT  = -mn * invT;           // x = d*invT + nmT in [0, T(+eps)]

            const float x0 = fmaxf(fmaf(d0, invT, nmT), 0.0f);
            const float x1 = fmaxf(fmaf(d1, invT, nmT), 0.0f);
            const float x2 = fmaxf(fmaf(d2, invT, nmT), 0.0f);
            const float x3 = fmaxf(fmaf(d3, invT, nmT), 0.0f);
            // no upper clamp needed: row 32 is a (g(1), 0) guard row; x <= 32+eps
            const int i0 = (int)x0;
            const int i1 = (int)x1;
            const int i2 = (int)x2;
            const int i3 = (int)x3;

            // conflict-free gathers
            const float2 e0 = tab[i0 * M_DIM + lane +  0];
            const float2 e1 = tab[i1 * M_DIM + lane + 32];
            const float2 e2 = tab[i2 * M_DIM + lane + 64];
            const float2 e3 = tab[i3 * M_DIM + lane + 96];
            const float fr0 = x0 - (float)i0;
            const float fr1 = x1 - (float)i1;
            const float fr2 = x2 - (float)i2;
            const float fr3 = x3 - (float)i3;

            // four coalesced 128B stores (lane-strided m layout)
            float* dst = outb + (size_t)n * M_DIM + lane;
            dst[ 0] = fmaf(fr0, e0.y, e0.x);
            dst[32] = fmaf(fr1, e1.y, e1.x);
            dst[64] = fmaf(fr2, e2.y, e2.x);
            dst[96] = fmaf(fr3, e3.y, e3.x);
        }
    }
}

extern "C" void kernel_launch(void* const* d_in, const int* in_sizes, int n_in,
                              void* d_out, int out_size) {
    const float* xyz = (const float*)d_in[0];
    const float* V   = (const float*)d_in[1];
    const float* W1  = (const float*)d_in[2];
    const float* b1  = (const float*)d_in[3];
    const float* W2  = (const float*)d_in[4];
    const float* b2  = (const float*)d_in[5];
    const float* W3  = (const float*)d_in[6];
    const float* b3  = (const float*)d_in[7];
    float* out = (float*)d_out;

    // Pass 1: build per-(b,t,m) scalar-function tables (33 rows incl. clamp row)
    const int total = B_DIM * T_ROWS * M_DIM;
    build_table<<<(total + 255) / 256, 256>>>(V, W1, b1, W2, b2, W3, b3);

    // Pass 2: 888 CTAs = 148 SMs x 6 resident — fill the SM with warps
    cudaFuncSetAttribute(featuration_kernel,
                         cudaFuncAttributeMaxDynamicSharedMemorySize, SMEM_BYTES);
    featuration_kernel<<<GRID_CTAS, THREADS, SMEM_BYTES>>>(xyz, V, out);
}